// round 9
// baseline (speedup 1.0000x reference)
#include <cuda_runtime.h>
#include <cuda_fp16.h>
#include <math.h>
#include <stdint.h>

#define D_MODEL 2048
#define KBANDS  64
#define WWIN    512
#define STRIDE  256
#define NCHUNK  32
#define SEQ     8192
#define NRET    8
#define NDATA   33

// ---------------- scratch ----------------------------------------------------
__device__ float g_P[NDATA * KBANDS * D_MODEL];   // A_L @ data_j
__device__ float g_Q[NDATA * KBANDS * D_MODEL];   // A_R @ data_j
__device__ float g_norms[NCHUNK * KBANDS];
__device__ float g_delta[KBANDS];
__device__ float g_vr[D_MODEL];
__device__ float g_vi[D_MODEL];
__device__ float g_ctx[D_MODEL];
__device__ int   g_top[NRET];
__device__ float g_cw[NRET];

// ---------------- helpers ----------------------------------------------------
__device__ __forceinline__ uint32_t saddr(const void* p) {
    return (uint32_t)__cvta_generic_to_shared(p);
}
__device__ __forceinline__ void ldsm4(uint32_t* r, uint32_t a) {
    asm volatile("ldmatrix.sync.aligned.m8n8.x4.shared.b16 {%0,%1,%2,%3}, [%4];"
                 : "=r"(r[0]), "=r"(r[1]), "=r"(r[2]), "=r"(r[3]) : "r"(a));
}
__device__ __forceinline__ void ldsm4t(uint32_t* r, uint32_t a) {
    asm volatile("ldmatrix.sync.aligned.m8n8.x4.trans.shared.b16 {%0,%1,%2,%3}, [%4];"
                 : "=r"(r[0]), "=r"(r[1]), "=r"(r[2]), "=r"(r[3]) : "r"(a));
}
__device__ __forceinline__ void mma16816(float* c, const uint32_t* a, uint32_t b0, uint32_t b1) {
    asm volatile("mma.sync.aligned.m16n8k16.row.col.f32.f16.f16.f32 "
                 "{%0,%1,%2,%3},{%4,%5,%6,%7},{%8,%9},{%0,%1,%2,%3};"
                 : "+f"(c[0]), "+f"(c[1]), "+f"(c[2]), "+f"(c[3])
                 : "r"(a[0]), "r"(a[1]), "r"(a[2]), "r"(a[3]), "r"(b0), "r"(b1));
}
__device__ __forceinline__ void split2h(float a, float b, uint32_t& hi, uint32_t& lo) {
    __half2 h = __floats2half2_rn(a, b);
    hi = *(uint32_t*)&h;
    float2 hf = __half22float2(h);
    __half2 l = __floats2half2_rn(a - hf.x, b - hf.y);
    lo = *(uint32_t*)&l;
}
__device__ __forceinline__ uint32_t pack2h(float a, float b) {
    __half2 h = __floats2half2_rn(a, b);
    return *(uint32_t*)&h;
}
__device__ __forceinline__ void cp16(uint32_t dst, const void* src) {
    asm volatile("cp.async.cg.shared.global [%0], [%1], 16;" :: "r"(dst), "l"(src));
}

// ---------------- K1: P/Q GEMM, fp16 2-pass + cp.async D pipeline ------------
// dynamic smem: sA 16KB | sD 8KB | stg0 16KB | stg1 16KB  = 56KB
__global__ __launch_bounds__(256, 2)
void pq_mma(const float* __restrict__ scan,
            const float* __restrict__ buf,
            const float* __restrict__ cheby) {
    extern __shared__ __align__(16) char smem[];
    __half* sA  = (__half*)smem;                 // 128x64 halves (hi segs0-3, lo segs4-7)
    __half* sD  = (__half*)(smem + 16384);       // 32x128 halves
    float* stg0 = (float*)(smem + 24576);        // 32x128 floats
    float* stg1 = (float*)(smem + 40960);        // 32x128 floats

    const int j = blockIdx.y;
    const int d0 = blockIdx.x * 128;
    const int tid = threadIdx.x;
    const int lane = tid & 31;
    const int warp = tid >> 5;
    const int wy = warp >> 1;
    const int wx = warp & 1;
    const int r = tid >> 3;      // D n-row 0..31
    const int sp = tid & 7;      // D 16-col group
    const float* scan1 = scan + (size_t)SEQ * D_MODEL;

    float acc[2][8][4];
#pragma unroll
    for (int a = 0; a < 2; a++)
#pragma unroll
        for (int f = 0; f < 8; f++)
#pragma unroll
            for (int q = 0; q < 4; q++) acc[a][f][q] = 0.0f;

    const uint32_t stg0a = saddr(stg0 + r * 128 + sp * 16);
    const uint32_t stg1a = saddr(stg1 + r * 128 + sp * 16);

    // issue cp.async for stage s
    auto cpD = [&](int s) {
        const int n = s * 32 + r;
        if (j == 0) {
            const float* src = buf + (size_t)(STRIDE + n) * D_MODEL + d0 + sp * 16;
#pragma unroll
            for (int q = 0; q < 4; q++) cp16(stg0a + q * 16, src + 4 * q);
        } else {
            const size_t g = (size_t)((j - 1) * STRIDE + n) * D_MODEL + d0 + sp * 16;
            const float* s0 = scan + g;
            const float* s1 = scan1 + g;
#pragma unroll
            for (int q = 0; q < 4; q++) {
                cp16(stg0a + q * 16, s0 + 4 * q);
                cp16(stg1a + q * 16, s1 + 4 * q);
            }
        }
        asm volatile("cp.async.commit_group;");
    };

    cpD(0);

    for (int s = 0; s < 8; s++) {
        asm volatile("cp.async.wait_group 0;");
        __syncthreads();
        // ---- A' tile fill (hi/lo split from cheby, L2-hot)
        {
            const int row = tid >> 1;
            const int kh = tid & 1;
            const int band = row & 63;
            const int koff = ((row >> 6) ? 256 : 0) + s * 32 + kh * 16;
            const float* src = cheby + band * WWIN + koff;
            uint32_t hi[8], lo[8];
#pragma unroll
            for (int q = 0; q < 4; q++) {
                float4 v = *(const float4*)(src + 4 * q);
                split2h(v.x, v.y, hi[2 * q], lo[2 * q]);
                split2h(v.z, v.w, hi[2 * q + 1], lo[2 * q + 1]);
            }
            const int s0 = kh * 2;
            const int r7 = row & 7;
            __half* rbase = sA + row * 64;
            *(uint4*)(rbase + (((s0    ) ^ r7) << 3)) = make_uint4(hi[0], hi[1], hi[2], hi[3]);
            *(uint4*)(rbase + (((s0 + 1) ^ r7) << 3)) = make_uint4(hi[4], hi[5], hi[6], hi[7]);
            *(uint4*)(rbase + (((s0 + 4) ^ r7) << 3)) = make_uint4(lo[0], lo[1], lo[2], lo[3]);
            *(uint4*)(rbase + (((s0 + 5) ^ r7) << 3)) = make_uint4(lo[4], lo[5], lo[6], lo[7]);
        }
        // ---- D convert from staged smem -> fp16 sD
        {
            float h[16];
            const float* p0 = stg0 + r * 128 + sp * 16;
#pragma unroll
            for (int q = 0; q < 4; q++) {
                float4 v = *(const float4*)(p0 + 4 * q);
                h[4 * q] = v.x; h[4 * q + 1] = v.y; h[4 * q + 2] = v.z; h[4 * q + 3] = v.w;
            }
            if (j != 0) {
                const float* p1 = stg1 + r * 128 + sp * 16;
#pragma unroll
                for (int q = 0; q < 4; q++) {
                    float4 v = *(const float4*)(p1 + 4 * q);
                    h[4 * q]     = 0.5f * (h[4 * q]     + v.x);
                    h[4 * q + 1] = 0.5f * (h[4 * q + 1] + v.y);
                    h[4 * q + 2] = 0.5f * (h[4 * q + 2] + v.z);
                    h[4 * q + 3] = 0.5f * (h[4 * q + 3] + v.w);
                }
            }
            uint32_t pk[8];
#pragma unroll
            for (int q = 0; q < 8; q++) pk[q] = pack2h(h[2 * q], h[2 * q + 1]);
            const int r7 = r & 7;
            const int s0 = sp * 2;
            *(uint4*)(sD + r * 128 + (((s0    ) ^ r7) << 3)) = make_uint4(pk[0], pk[1], pk[2], pk[3]);
            *(uint4*)(sD + r * 128 + (((s0 + 1) ^ r7) << 3)) = make_uint4(pk[4], pk[5], pk[6], pk[7]);
        }
        __syncthreads();
        if (s < 7) cpD(s + 1);   // overlaps with MMA below

        // ---- MMA phase
#pragma unroll
        for (int kk = 0; kk < 2; kk++) {
            uint32_t ah[2][4], al[2][4];
#pragma unroll
            for (int t16 = 0; t16 < 2; t16++) {
                const int row = wy * 32 + t16 * 16 + (lane & 15);
                const int sg = kk * 2 + (lane >> 4);
                const int r7 = row & 7;
                ldsm4(ah[t16], saddr(sA + row * 64 + (((sg    ) ^ r7) << 3)));
                ldsm4(al[t16], saddr(sA + row * 64 + (((sg + 4) ^ r7) << 3)));
            }
#pragma unroll
            for (int g = 0; g < 4; g++) {
                const int rn = kk * 16 + (lane & 15);
                const int sg = wx * 8 + g * 2 + (lane >> 4);
                const int off = rn * 128 + ((sg ^ (rn & 7)) << 3);
                uint32_t bh[4];
                ldsm4t(bh, saddr(sD + off));
#pragma unroll
                for (int t16 = 0; t16 < 2; t16++) {
                    mma16816(acc[t16][2 * g],     ah[t16], bh[0], bh[1]);
                    mma16816(acc[t16][2 * g + 1], ah[t16], bh[2], bh[3]);
                    mma16816(acc[t16][2 * g],     al[t16], bh[0], bh[1]);
                    mma16816(acc[t16][2 * g + 1], al[t16], bh[2], bh[3]);
                }
            }
        }
    }

    // ---- epilogue
    const float sc = 2.0f / (float)WWIN;
#pragma unroll
    for (int t16 = 0; t16 < 2; t16++) {
        const int m = wy * 32 + t16 * 16 + (lane >> 2);
        const float s0 = (m == 0 || m == 64) ? sc * 0.5f : sc;
        float* base = (m < 64) ? (g_P + (((size_t)(j * 64 + m)) << 11))
                               : (g_Q + (((size_t)(j * 64 + (m - 64))) << 11));
#pragma unroll
        for (int f = 0; f < 8; f++) {
            const int col = d0 + wx * 64 + f * 8 + (lane & 3) * 2;
            *(float2*)(base + col) = make_float2(acc[t16][f][0] * s0, acc[t16][f][1] * s0);
            *(float2*)(base + col + (8 << 11)) = make_float2(acc[t16][f][2] * sc, acc[t16][f][3] * sc);
        }
    }
}

// ---------------- K2: norms (+ final delta, + zero vr/vi) --------------------
__global__ __launch_bounds__(256)
void norms2_kernel() {
    __shared__ float sh[8];
    const int ik = blockIdx.x;
    const int t = threadIdx.x;
    const int i = ik >> 6, k = ik & 63;

    if (ik < 8) g_vr[ik * 256 + t] = 0.0f;
    else if (ik < 16) g_vi[(ik - 8) * 256 + t] = 0.0f;

    const float4* p = (const float4*)(g_P + (((size_t)(i * 64 + k)) << 11));
    const float4* q = (const float4*)(g_Q + (((size_t)((i + 1) * 64 + k)) << 11));
    const bool last = (i == NCHUNK - 1);
    const float4* pp = (const float4*)(g_P + (((size_t)(30 * 64 + k)) << 11));
    const float4* qp = (const float4*)(g_Q + (((size_t)(31 * 64 + k)) << 11));
    float s = 0.0f, dl = 0.0f;
#pragma unroll
    for (int it = 0; it < 2; it++) {
        float4 a = p[t + 256 * it], b = q[t + 256 * it];
        float cx = a.x + b.x, cy = a.y + b.y, cz = a.z + b.z, cw = a.w + b.w;
        s += cx * cx + cy * cy + cz * cz + cw * cw;
        if (last) {
            float4 c = pp[t + 256 * it], d = qp[t + 256 * it];
            float ex = cx - c.x - d.x, ey = cy - c.y - d.y;
            float ez = cz - c.z - d.z, ew = cw - c.w - d.w;
            dl += ex * ex + ey * ey + ez * ez + ew * ew;
        }
    }
    const int lane = t & 31, w = t >> 5;
#pragma unroll
    for (int o = 16; o > 0; o >>= 1) s += __shfl_down_sync(0xffffffffu, s, o);
    if (lane == 0) sh[w] = s;
    __syncthreads();
    if (t == 0) {
        float tot = 0.0f;
#pragma unroll
        for (int jj = 0; jj < 8; jj++) tot += sh[jj];
        g_norms[ik] = fmaxf(sqrtf(tot), 1e-12f);
    }
    if (last) {
        __syncthreads();
#pragma unroll
        for (int o = 16; o > 0; o >>= 1) dl += __shfl_down_sync(0xffffffffu, dl, o);
        if (lane == 0) sh[w] = dl;
        __syncthreads();
        if (t == 0) {
            float tot = 0.0f;
#pragma unroll
            for (int jj = 0; jj < 8; jj++) tot += sh[jj];
            g_delta[k] = sqrtf(tot);
        }
    }
}

// ---------------- K3: fused T-EMA + bind, k-split x4 -------------------------
__global__ __launch_bounds__(256)
void tbind_kernel(const float* __restrict__ rr, const float* __restrict__ ri) {
    const int i = blockIdx.x;
    const int d = (blockIdx.y << 8) + threadIdx.x;
    const int k0 = blockIdx.z << 4;
    __shared__ float winv[16];
    if (threadIdx.x < 16) {
        float w = 0.1f;
        for (int jj = i; jj < NCHUNK - 1; jj++) w *= 0.9f;
        winv[threadIdx.x] = w / g_norms[(i << 6) + k0 + threadIdx.x];
    }
    __syncthreads();
    float vr = 0.0f, vi = 0.0f;
#pragma unroll
    for (int kk = 0; kk < 16; kk++) {
        const int k = k0 + kk;
        const float c = g_P[(((size_t)((i << 6) | k)) << 11) + d] +
                        g_Q[(((size_t)(((i + 1) << 6) | k)) << 11) + d];
        const float wv = winv[kk] * c;
        vr = fmaf(wv, rr[((size_t)k << 11) + d], vr);
        vi = fmaf(wv, ri[((size_t)k << 11) + d], vi);
    }
    atomicAdd(&g_vr[d], vr);
    atomicAdd(&g_vi[d], vi);
}

// ---------------- K4a: scalars (cnorms EMA + parallel top-8) -----------------
__global__ void scalars_kernel(const float* __restrict__ wb, float* __restrict__ out) {
    __shared__ float sDelta[64], sCn[64];
    const int t = threadIdx.x;  // 64 threads
    float c = 0.0f;
#pragma unroll
    for (int i = 0; i < NCHUNK; i++) c = 0.9f * c + 0.1f * g_norms[(i << 6) + t];
    sCn[t] = c;
    const float dv = g_delta[t];
    sDelta[t] = dv;
    out[D_MODEL + t] = dv;
    __syncthreads();
    if (t < 32) {
        for (int jj = 0; jj < NRET; jj++) {
            float v0 = sDelta[t], v1 = sDelta[t + 32];
            int bi = (v1 > v0) ? (t + 32) : t;
            float bv = fmaxf(v0, v1);
#pragma unroll
            for (int o = 16; o > 0; o >>= 1) {
                float ov = __shfl_down_sync(0xffffffffu, bv, o);
                int oi = __shfl_down_sync(0xffffffffu, bi, o);
                if (ov > bv) { bv = ov; bi = oi; }
            }
            bi = __shfl_sync(0xffffffffu, bi, 0);
            if (t == 0) {
                g_top[jj] = bi;
                g_cw[jj] = log1pf(expf(wb[bi])) * fmaxf(sCn[bi], 1e-12f);
                sDelta[bi] = -3.4e38f;
            }
            __syncwarp();
        }
    }
}

// ---------------- K4b: ctx + vr/vi outputs -----------------------------------
__global__ __launch_bounds__(128)
void ctx_kernel(const float* __restrict__ rr, const float* __restrict__ ri,
                float* __restrict__ out) {
    const int d = (blockIdx.x << 7) + threadIdx.x;
    const float vr = g_vr[d], vi = g_vi[d];
    float c = 0.0f;
#pragma unroll
    for (int jj = 0; jj < NRET; jj++) {
        const int tp = g_top[jj];
        c = fmaf(g_cw[jj], fmaf(vr, rr[((size_t)tp << 11) + d], vi * ri[((size_t)tp << 11) + d]), c);
    }
    g_ctx[d] = c;
    out[D_MODEL + KBANDS + d] = vr;
    out[2 * D_MODEL + KBANDS + d] = vi;
}

// ---------------- K5: output projection --------------------------------------
__global__ __launch_bounds__(128)
void proj_kernel(const float* __restrict__ wp, const float* __restrict__ gate,
                 float* __restrict__ out) {
    __shared__ float sh[4];
    const int row = blockIdx.x;
    const int t = threadIdx.x;
    const float4* w = (const float4*)(wp + ((size_t)row << 11));
    const float4* cx = (const float4*)g_ctx;
    float s = 0.0f;
#pragma unroll
    for (int it = 0; it < 4; it++) {
        float4 a = w[t + 128 * it], b = cx[t + 128 * it];
        s += a.x * b.x + a.y * b.y + a.z * b.z + a.w * b.w;
    }
#pragma unroll
    for (int o = 16; o > 0; o >>= 1) s += __shfl_down_sync(0xffffffffu, s, o);
    if ((t & 31) == 0) sh[t >> 5] = s;
    __syncthreads();
    if (t == 0) {
        const float tot = sh[0] + sh[1] + sh[2] + sh[3];
        out[row] = tot * (1.0f / (1.0f + expf(-gate[0])));
    }
}

// ---------------- launch ------------------------------------------------------
extern "C" void kernel_launch(void* const* d_in, const int* in_sizes, int n_in,
                              void* d_out, int out_size) {
    const float* scan  = (const float*)d_in[0];
    const float* buf   = (const float*)d_in[1];
    const float* rr    = (const float*)d_in[2];
    const float* ri    = (const float*)d_in[3];
    const float* wb    = (const float*)d_in[4];
    const float* wp    = (const float*)d_in[5];
    const float* gate  = (const float*)d_in[6];
    const float* cheby = (const float*)d_in[7];
    float* out = (float*)d_out;

    static cudaStream_t s_side = nullptr;
    static cudaEvent_t ev_fork = nullptr, ev_join = nullptr;
    static bool init_done = false;
    if (!init_done) {
        cudaStreamCreateWithFlags(&s_side, cudaStreamNonBlocking);
        cudaEventCreateWithFlags(&ev_fork, cudaEventDisableTiming);
        cudaEventCreateWithFlags(&ev_join, cudaEventDisableTiming);
        cudaFuncSetAttribute(pq_mma, cudaFuncAttributeMaxDynamicSharedMemorySize, 57344);
        init_done = true;
    }

    pq_mma<<<dim3(16, NDATA), 256, 57344>>>(scan, buf, cheby);
    norms2_kernel<<<NCHUNK * KBANDS, 256>>>();

    // fork: scalars (needs norms/delta only) runs concurrently with tbind
    cudaEventRecord(ev_fork, 0);
    cudaStreamWaitEvent(s_side, ev_fork, 0);
    scalars_kernel<<<1, 64, 0, s_side>>>(wb, out);
    tbind_kernel<<<dim3(NCHUNK, 8, 4), 256>>>(rr, ri);
    cudaEventRecord(ev_join, s_side);
    cudaStreamWaitEvent(0, ev_join, 0);

    ctx_kernel<<<16, 128>>>(rr, ri, out);
    proj_kernel<<<D_MODEL, 128>>>(wp, gate, out);
}

// round 11
// speedup vs baseline: 1.1564x; 1.1564x over previous
#include <cuda_runtime.h>
#include <cuda_fp16.h>
#include <math.h>
#include <stdint.h>

#define D_MODEL 2048
#define KBANDS  64
#define WWIN    512
#define STRIDE  256
#define NCHUNK  32
#define SEQ     8192
#define NRET    8
#define NDATA   33

// ---------------- scratch ----------------------------------------------------
__device__ float g_P[NDATA * KBANDS * D_MODEL];   // A_L @ data_j
__device__ float g_Q[NDATA * KBANDS * D_MODEL];   // A_R @ data_j
__device__ float g_norms[NCHUNK * KBANDS];
__device__ float g_delta[KBANDS];
__device__ float g_vr[D_MODEL];
__device__ float g_vi[D_MODEL];
__device__ float g_ctx[D_MODEL];
__device__ int   g_top[NRET];
__device__ float g_cw[NRET];

// ---------------- helpers ----------------------------------------------------
__device__ __forceinline__ uint32_t saddr(const void* p) {
    return (uint32_t)__cvta_generic_to_shared(p);
}
__device__ __forceinline__ void ldsm4(uint32_t* r, uint32_t a) {
    asm volatile("ldmatrix.sync.aligned.m8n8.x4.shared.b16 {%0,%1,%2,%3}, [%4];"
                 : "=r"(r[0]), "=r"(r[1]), "=r"(r[2]), "=r"(r[3]) : "r"(a));
}
__device__ __forceinline__ void ldsm4t(uint32_t* r, uint32_t a) {
    asm volatile("ldmatrix.sync.aligned.m8n8.x4.trans.shared.b16 {%0,%1,%2,%3}, [%4];"
                 : "=r"(r[0]), "=r"(r[1]), "=r"(r[2]), "=r"(r[3]) : "r"(a));
}
__device__ __forceinline__ void mma16816(float* c, const uint32_t* a, uint32_t b0, uint32_t b1) {
    asm volatile("mma.sync.aligned.m16n8k16.row.col.f32.f16.f16.f32 "
                 "{%0,%1,%2,%3},{%4,%5,%6,%7},{%8,%9},{%0,%1,%2,%3};"
                 : "+f"(c[0]), "+f"(c[1]), "+f"(c[2]), "+f"(c[3])
                 : "r"(a[0]), "r"(a[1]), "r"(a[2]), "r"(a[3]), "r"(b0), "r"(b1));
}
__device__ __forceinline__ uint32_t pack2h(float a, float b) {
    __half2 h = __floats2half2_rn(a, b);
    return *(uint32_t*)&h;
}

// ---------------- K1: P/Q GEMM, single-pass fp16 -----------------------------
__global__ __launch_bounds__(256, 2)
void pq_mma(const float* __restrict__ scan,
            const float* __restrict__ buf,
            const float* __restrict__ cheby) {
    __shared__ __align__(16) __half sA[128 * 64];    // 16 KB (only "hi" segs used)
    __shared__ __align__(16) __half sD[32 * 128];    // 8 KB

    const int j = blockIdx.y;
    const int d0 = blockIdx.x * 128;
    const int tid = threadIdx.x;
    const int lane = tid & 31;
    const int warp = tid >> 5;
    const int wy = warp >> 1;
    const int wx = warp & 1;
    const float* scan1 = scan + (size_t)SEQ * D_MODEL;

    float acc[2][8][4];
#pragma unroll
    for (int a = 0; a < 2; a++)
#pragma unroll
        for (int f = 0; f < 8; f++)
#pragma unroll
            for (int q = 0; q < 4; q++) acc[a][f][q] = 0.0f;

    for (int s = 0; s < 8; s++) {
        __syncthreads();
        // ---- A' tile fill (single fp16, swizzled)
        {
            const int row = tid >> 1;
            const int kh = tid & 1;
            const int band = row & 63;
            const int koff = ((row >> 6) ? 256 : 0) + s * 32 + kh * 16;
            const float* src = cheby + band * WWIN + koff;
            uint32_t pk[8];
#pragma unroll
            for (int q = 0; q < 4; q++) {
                float4 v = *(const float4*)(src + 4 * q);
                pk[2 * q]     = pack2h(v.x, v.y);
                pk[2 * q + 1] = pack2h(v.z, v.w);
            }
            const int s0 = kh * 2;
            const int r7 = row & 7;
            __half* rbase = sA + row * 64;
            *(uint4*)(rbase + (((s0    ) ^ r7) << 3)) = make_uint4(pk[0], pk[1], pk[2], pk[3]);
            *(uint4*)(rbase + (((s0 + 1) ^ r7) << 3)) = make_uint4(pk[4], pk[5], pk[6], pk[7]);
        }
        // ---- D tile fill (single fp16)
        {
            const int r = tid >> 3;
            const int sp = tid & 7;
            const int n = s * 32 + r;
            float h[16];
            if (j == 0) {
                const float* p0 = buf + (size_t)(STRIDE + n) * D_MODEL + d0 + sp * 16;
#pragma unroll
                for (int q = 0; q < 4; q++) {
                    float4 v = *(const float4*)(p0 + 4 * q);
                    h[4 * q] = v.x; h[4 * q + 1] = v.y; h[4 * q + 2] = v.z; h[4 * q + 3] = v.w;
                }
            } else {
                const size_t g = (size_t)((j - 1) * STRIDE + n) * D_MODEL + d0 + sp * 16;
                const float* p0 = scan + g;
                const float* p1 = scan1 + g;
#pragma unroll
                for (int q = 0; q < 4; q++) {
                    float4 a = *(const float4*)(p0 + 4 * q);
                    float4 b = *(const float4*)(p1 + 4 * q);
                    h[4 * q]     = 0.5f * (a.x + b.x);
                    h[4 * q + 1] = 0.5f * (a.y + b.y);
                    h[4 * q + 2] = 0.5f * (a.z + b.z);
                    h[4 * q + 3] = 0.5f * (a.w + b.w);
                }
            }
            uint32_t pk[8];
#pragma unroll
            for (int q = 0; q < 8; q++) pk[q] = pack2h(h[2 * q], h[2 * q + 1]);
            const int r7 = r & 7;
            const int s0 = sp * 2;
            *(uint4*)(sD + r * 128 + (((s0    ) ^ r7) << 3)) = make_uint4(pk[0], pk[1], pk[2], pk[3]);
            *(uint4*)(sD + r * 128 + (((s0 + 1) ^ r7) << 3)) = make_uint4(pk[4], pk[5], pk[6], pk[7]);
        }
        __syncthreads();

#pragma unroll
        for (int kk = 0; kk < 2; kk++) {
            uint32_t ah[2][4];
#pragma unroll
            for (int t16 = 0; t16 < 2; t16++) {
                const int row = wy * 32 + t16 * 16 + (lane & 15);
                const int sg = kk * 2 + (lane >> 4);
                const int r7 = row & 7;
                ldsm4(ah[t16], saddr(sA + row * 64 + ((sg ^ r7) << 3)));
            }
#pragma unroll
            for (int g = 0; g < 4; g++) {
                const int rn = kk * 16 + (lane & 15);
                const int sg = wx * 8 + g * 2 + (lane >> 4);
                const int off = rn * 128 + ((sg ^ (rn & 7)) << 3);
                uint32_t bh[4];
                ldsm4t(bh, saddr(sD + off));
#pragma unroll
                for (int t16 = 0; t16 < 2; t16++) {
                    mma16816(acc[t16][2 * g],     ah[t16], bh[0], bh[1]);
                    mma16816(acc[t16][2 * g + 1], ah[t16], bh[2], bh[3]);
                }
            }
        }
    }

    // ---- epilogue
    const float sc = 2.0f / (float)WWIN;
#pragma unroll
    for (int t16 = 0; t16 < 2; t16++) {
        const int m = wy * 32 + t16 * 16 + (lane >> 2);
        const float s0 = (m == 0 || m == 64) ? sc * 0.5f : sc;
        float* base = (m < 64) ? (g_P + (((size_t)(j * 64 + m)) << 11))
                               : (g_Q + (((size_t)(j * 64 + (m - 64))) << 11));
#pragma unroll
        for (int f = 0; f < 8; f++) {
            const int col = d0 + wx * 64 + f * 8 + (lane & 3) * 2;
            *(float2*)(base + col) = make_float2(acc[t16][f][0] * s0, acc[t16][f][1] * s0);
            *(float2*)(base + col + (8 << 11)) = make_float2(acc[t16][f][2] * sc, acc[t16][f][3] * sc);
        }
    }
}

// ---------------- K2: norms (+ final delta, + zero vr/vi) --------------------
__global__ __launch_bounds__(256)
void norms2_kernel() {
    __shared__ float sh[8];
    const int ik = blockIdx.x;
    const int t = threadIdx.x;
    const int i = ik >> 6, k = ik & 63;

    if (ik < 8) g_vr[ik * 256 + t] = 0.0f;
    else if (ik < 16) g_vi[(ik - 8) * 256 + t] = 0.0f;

    const float4* p = (const float4*)(g_P + (((size_t)(i * 64 + k)) << 11));
    const float4* q = (const float4*)(g_Q + (((size_t)((i + 1) * 64 + k)) << 11));
    const bool last = (i == NCHUNK - 1);
    const float4* pp = (const float4*)(g_P + (((size_t)(30 * 64 + k)) << 11));
    const float4* qp = (const float4*)(g_Q + (((size_t)(31 * 64 + k)) << 11));
    float s = 0.0f, dl = 0.0f;
#pragma unroll
    for (int it = 0; it < 2; it++) {
        float4 a = p[t + 256 * it], b = q[t + 256 * it];
        float cx = a.x + b.x, cy = a.y + b.y, cz = a.z + b.z, cw = a.w + b.w;
        s += cx * cx + cy * cy + cz * cz + cw * cw;
        if (last) {
            float4 c = pp[t + 256 * it], d = qp[t + 256 * it];
            float ex = cx - c.x - d.x, ey = cy - c.y - d.y;
            float ez = cz - c.z - d.z, ew = cw - c.w - d.w;
            dl += ex * ex + ey * ey + ez * ez + ew * ew;
        }
    }
    const int lane = t & 31, w = t >> 5;
#pragma unroll
    for (int o = 16; o > 0; o >>= 1) s += __shfl_down_sync(0xffffffffu, s, o);
    if (lane == 0) sh[w] = s;
    __syncthreads();
    if (t == 0) {
        float tot = 0.0f;
#pragma unroll
        for (int jj = 0; jj < 8; jj++) tot += sh[jj];
        g_norms[ik] = fmaxf(sqrtf(tot), 1e-12f);
    }
    if (last) {
        __syncthreads();
#pragma unroll
        for (int o = 16; o > 0; o >>= 1) dl += __shfl_down_sync(0xffffffffu, dl, o);
        if (lane == 0) sh[w] = dl;
        __syncthreads();
        if (t == 0) {
            float tot = 0.0f;
#pragma unroll
            for (int jj = 0; jj < 8; jj++) tot += sh[jj];
            g_delta[k] = sqrtf(tot);
        }
    }
}

// ---------------- K3: fused T-EMA + bind, k-split x4 -------------------------
__global__ __launch_bounds__(256)
void tbind_kernel(const float* __restrict__ rr, const float* __restrict__ ri) {
    const int i = blockIdx.x;
    const int d = (blockIdx.y << 8) + threadIdx.x;
    const int k0 = blockIdx.z << 4;
    __shared__ float winv[16];
    if (threadIdx.x < 16) {
        float w = 0.1f;
        for (int jj = i; jj < NCHUNK - 1; jj++) w *= 0.9f;
        winv[threadIdx.x] = w / g_norms[(i << 6) + k0 + threadIdx.x];
    }
    __syncthreads();
    float vr = 0.0f, vi = 0.0f;
#pragma unroll
    for (int kk = 0; kk < 16; kk++) {
        const int k = k0 + kk;
        const float c = g_P[(((size_t)((i << 6) | k)) << 11) + d] +
                        g_Q[(((size_t)(((i + 1) << 6) | k)) << 11) + d];
        const float wv = winv[kk] * c;
        vr = fmaf(wv, rr[((size_t)k << 11) + d], vr);
        vi = fmaf(wv, ri[((size_t)k << 11) + d], vi);
    }
    atomicAdd(&g_vr[d], vr);
    atomicAdd(&g_vi[d], vi);
}

// ---------------- K4a: scalars (cnorms EMA + parallel top-8) -----------------
__global__ void scalars_kernel(const float* __restrict__ wb, float* __restrict__ out) {
    __shared__ float sDelta[64], sCn[64];
    const int t = threadIdx.x;  // 64 threads
    float c = 0.0f;
#pragma unroll
    for (int i = 0; i < NCHUNK; i++) c = 0.9f * c + 0.1f * g_norms[(i << 6) + t];
    sCn[t] = c;
    const float dv = g_delta[t];
    sDelta[t] = dv;
    out[D_MODEL + t] = dv;
    __syncthreads();
    if (t < 32) {
        for (int jj = 0; jj < NRET; jj++) {
            float v0 = sDelta[t], v1 = sDelta[t + 32];
            int bi = (v1 > v0) ? (t + 32) : t;
            float bv = fmaxf(v0, v1);
#pragma unroll
            for (int o = 16; o > 0; o >>= 1) {
                float ov = __shfl_down_sync(0xffffffffu, bv, o);
                int oi = __shfl_down_sync(0xffffffffu, bi, o);
                if (ov > bv) { bv = ov; bi = oi; }
            }
            bi = __shfl_sync(0xffffffffu, bi, 0);
            if (t == 0) {
                g_top[jj] = bi;
                g_cw[jj] = log1pf(expf(wb[bi])) * fmaxf(sCn[bi], 1e-12f);
                sDelta[bi] = -3.4e38f;
            }
            __syncwarp();
        }
    }
}

// ---------------- K4b: ctx + vr/vi outputs -----------------------------------
__global__ __launch_bounds__(128)
void ctx_kernel(const float* __restrict__ rr, const float* __restrict__ ri,
                float* __restrict__ out) {
    const int d = (blockIdx.x << 7) + threadIdx.x;
    const float vr = g_vr[d], vi = g_vi[d];
    float c = 0.0f;
#pragma unroll
    for (int jj = 0; jj < NRET; jj++) {
        const int tp = g_top[jj];
        c = fmaf(g_cw[jj], fmaf(vr, rr[((size_t)tp << 11) + d], vi * ri[((size_t)tp << 11) + d]), c);
    }
    g_ctx[d] = c;
    out[D_MODEL + KBANDS + d] = vr;
    out[2 * D_MODEL + KBANDS + d] = vi;
}

// ---------------- K5: output projection --------------------------------------
__global__ __launch_bounds__(128)
void proj_kernel(const float* __restrict__ wp, const float* __restrict__ gate,
                 float* __restrict__ out) {
    __shared__ float sh[4];
    const int row = blockIdx.x;
    const int t = threadIdx.x;
    const float4* w = (const float4*)(wp + ((size_t)row << 11));
    const float4* cx = (const float4*)g_ctx;
    float s = 0.0f;
#pragma unroll
    for (int it = 0; it < 4; it++) {
        float4 a = w[t + 128 * it], b = cx[t + 128 * it];
        s += a.x * b.x + a.y * b.y + a.z * b.z + a.w * b.w;
    }
#pragma unroll
    for (int o = 16; o > 0; o >>= 1) s += __shfl_down_sync(0xffffffffu, s, o);
    if ((t & 31) == 0) sh[t >> 5] = s;
    __syncthreads();
    if (t == 0) {
        const float tot = sh[0] + sh[1] + sh[2] + sh[3];
        out[row] = tot * (1.0f / (1.0f + expf(-gate[0])));
    }
}

// ---------------- launch ------------------------------------------------------
extern "C" void kernel_launch(void* const* d_in, const int* in_sizes, int n_in,
                              void* d_out, int out_size) {
    const float* scan  = (const float*)d_in[0];
    const float* buf   = (const float*)d_in[1];
    const float* rr    = (const float*)d_in[2];
    const float* ri    = (const float*)d_in[3];
    const float* wb    = (const float*)d_in[4];
    const float* wp    = (const float*)d_in[5];
    const float* gate  = (const float*)d_in[6];
    const float* cheby = (const float*)d_in[7];
    float* out = (float*)d_out;

    static cudaStream_t s_side = nullptr;
    static cudaEvent_t ev_fork = nullptr, ev_join = nullptr;
    static bool init_done = false;
    if (!init_done) {
        cudaStreamCreateWithFlags(&s_side, cudaStreamNonBlocking);
        cudaEventCreateWithFlags(&ev_fork, cudaEventDisableTiming);
        cudaEventCreateWithFlags(&ev_join, cudaEventDisableTiming);
        init_done = true;
    }

    pq_mma<<<dim3(16, NDATA), 256>>>(scan, buf, cheby);
    norms2_kernel<<<NCHUNK * KBANDS, 256>>>();

    cudaEventRecord(ev_fork, 0);
    cudaStreamWaitEvent(s_side, ev_fork, 0);
    scalars_kernel<<<1, 64, 0, s_side>>>(wb, out);
    tbind_kernel<<<dim3(NCHUNK, 8, 4), 256>>>(rr, ri);
    cudaEventRecord(ev_join, s_side);
    cudaStreamWaitEvent(0, ev_join, 0);

    ctx_kernel<<<16, 128>>>(rr, ri, out);
    proj_kernel<<<D_MODEL, 128>>>(wp, gate, out);
}

// round 12
// speedup vs baseline: 1.1877x; 1.0271x over previous
#include <cuda_runtime.h>
#include <cuda_fp16.h>
#include <math.h>
#include <stdint.h>

#define D_MODEL 2048
#define KBANDS  64
#define WWIN    512
#define STRIDE  256
#define NCHUNK  32
#define SEQ     8192
#define NRET    8
#define NDATA   33

// ---------------- scratch ----------------------------------------------------
__device__ __half g_P[NDATA * KBANDS * D_MODEL];   // A_L @ data_j (fp16)
__device__ __half g_Q[NDATA * KBANDS * D_MODEL];   // A_R @ data_j (fp16)
__device__ float g_norms[NCHUNK * KBANDS];
__device__ float g_delta[KBANDS];
__device__ float g_vr[D_MODEL];
__device__ float g_vi[D_MODEL];
__device__ float g_ctx[D_MODEL];
__device__ int   g_top[NRET];
__device__ float g_cw[NRET];

// ---------------- helpers ----------------------------------------------------
__device__ __forceinline__ uint32_t saddr(const void* p) {
    return (uint32_t)__cvta_generic_to_shared(p);
}
__device__ __forceinline__ void ldsm4(uint32_t* r, uint32_t a) {
    asm volatile("ldmatrix.sync.aligned.m8n8.x4.shared.b16 {%0,%1,%2,%3}, [%4];"
                 : "=r"(r[0]), "=r"(r[1]), "=r"(r[2]), "=r"(r[3]) : "r"(a));
}
__device__ __forceinline__ void ldsm4t(uint32_t* r, uint32_t a) {
    asm volatile("ldmatrix.sync.aligned.m8n8.x4.trans.shared.b16 {%0,%1,%2,%3}, [%4];"
                 : "=r"(r[0]), "=r"(r[1]), "=r"(r[2]), "=r"(r[3]) : "r"(a));
}
__device__ __forceinline__ void mma16816(float* c, const uint32_t* a, uint32_t b0, uint32_t b1) {
    asm volatile("mma.sync.aligned.m16n8k16.row.col.f32.f16.f16.f32 "
                 "{%0,%1,%2,%3},{%4,%5,%6,%7},{%8,%9},{%0,%1,%2,%3};"
                 : "+f"(c[0]), "+f"(c[1]), "+f"(c[2]), "+f"(c[3])
                 : "r"(a[0]), "r"(a[1]), "r"(a[2]), "r"(a[3]), "r"(b0), "r"(b1));
}
__device__ __forceinline__ uint32_t pack2h(float a, float b) {
    __half2 h = __floats2half2_rn(a, b);
    return *(uint32_t*)&h;
}
__device__ __forceinline__ float2 h2f(uint32_t bits) {
    return __half22float2(*(__half2*)&bits);
}

// ---------------- K1: P/Q GEMM, single-pass fp16, fp16 output ----------------
__global__ __launch_bounds__(256, 2)
void pq_mma(const float* __restrict__ scan,
            const float* __restrict__ buf,
            const float* __restrict__ cheby) {
    __shared__ __align__(16) __half sA[128 * 64];    // 16 KB
    __shared__ __align__(16) __half sD[32 * 128];    // 8 KB

    const int j = blockIdx.y;
    const int d0 = blockIdx.x * 128;
    const int tid = threadIdx.x;
    const int lane = tid & 31;
    const int warp = tid >> 5;
    const int wy = warp >> 1;
    const int wx = warp & 1;
    const float* scan1 = scan + (size_t)SEQ * D_MODEL;

    float acc[2][8][4];
#pragma unroll
    for (int a = 0; a < 2; a++)
#pragma unroll
        for (int f = 0; f < 8; f++)
#pragma unroll
            for (int q = 0; q < 4; q++) acc[a][f][q] = 0.0f;

    for (int s = 0; s < 8; s++) {
        __syncthreads();
        // ---- A' tile fill (single fp16, swizzled)
        {
            const int row = tid >> 1;
            const int kh = tid & 1;
            const int band = row & 63;
            const int koff = ((row >> 6) ? 256 : 0) + s * 32 + kh * 16;
            const float* src = cheby + band * WWIN + koff;
            uint32_t pk[8];
#pragma unroll
            for (int q = 0; q < 4; q++) {
                float4 v = *(const float4*)(src + 4 * q);
                pk[2 * q]     = pack2h(v.x, v.y);
                pk[2 * q + 1] = pack2h(v.z, v.w);
            }
            const int s0 = kh * 2;
            const int r7 = row & 7;
            __half* rbase = sA + row * 64;
            *(uint4*)(rbase + (((s0    ) ^ r7) << 3)) = make_uint4(pk[0], pk[1], pk[2], pk[3]);
            *(uint4*)(rbase + (((s0 + 1) ^ r7) << 3)) = make_uint4(pk[4], pk[5], pk[6], pk[7]);
        }
        // ---- D tile fill (single fp16)
        {
            const int r = tid >> 3;
            const int sp = tid & 7;
            const int n = s * 32 + r;
            float h[16];
            if (j == 0) {
                const float* p0 = buf + (size_t)(STRIDE + n) * D_MODEL + d0 + sp * 16;
#pragma unroll
                for (int q = 0; q < 4; q++) {
                    float4 v = *(const float4*)(p0 + 4 * q);
                    h[4 * q] = v.x; h[4 * q + 1] = v.y; h[4 * q + 2] = v.z; h[4 * q + 3] = v.w;
                }
            } else {
                const size_t g = (size_t)((j - 1) * STRIDE + n) * D_MODEL + d0 + sp * 16;
                const float* p0 = scan + g;
                const float* p1 = scan1 + g;
#pragma unroll
                for (int q = 0; q < 4; q++) {
                    float4 a = *(const float4*)(p0 + 4 * q);
                    float4 b = *(const float4*)(p1 + 4 * q);
                    h[4 * q]     = 0.5f * (a.x + b.x);
                    h[4 * q + 1] = 0.5f * (a.y + b.y);
                    h[4 * q + 2] = 0.5f * (a.z + b.z);
                    h[4 * q + 3] = 0.5f * (a.w + b.w);
                }
            }
            uint32_t pk[8];
#pragma unroll
            for (int q = 0; q < 8; q++) pk[q] = pack2h(h[2 * q], h[2 * q + 1]);
            const int r7 = r & 7;
            const int s0 = sp * 2;
            *(uint4*)(sD + r * 128 + (((s0    ) ^ r7) << 3)) = make_uint4(pk[0], pk[1], pk[2], pk[3]);
            *(uint4*)(sD + r * 128 + (((s0 + 1) ^ r7) << 3)) = make_uint4(pk[4], pk[5], pk[6], pk[7]);
        }
        __syncthreads();

#pragma unroll
        for (int kk = 0; kk < 2; kk++) {
            uint32_t ah[2][4];
#pragma unroll
            for (int t16 = 0; t16 < 2; t16++) {
                const int row = wy * 32 + t16 * 16 + (lane & 15);
                const int sg = kk * 2 + (lane >> 4);
                const int r7 = row & 7;
                ldsm4(ah[t16], saddr(sA + row * 64 + ((sg ^ r7) << 3)));
            }
#pragma unroll
            for (int g = 0; g < 4; g++) {
                const int rn = kk * 16 + (lane & 15);
                const int sg = wx * 8 + g * 2 + (lane >> 4);
                const int off = rn * 128 + ((sg ^ (rn & 7)) << 3);
                uint32_t bh[4];
                ldsm4t(bh, saddr(sD + off));
#pragma unroll
                for (int t16 = 0; t16 < 2; t16++) {
                    mma16816(acc[t16][2 * g],     ah[t16], bh[0], bh[1]);
                    mma16816(acc[t16][2 * g + 1], ah[t16], bh[2], bh[3]);
                }
            }
        }
    }

    // ---- epilogue: scaled fp16 stores
    const float sc = 2.0f / (float)WWIN;
#pragma unroll
    for (int t16 = 0; t16 < 2; t16++) {
        const int m = wy * 32 + t16 * 16 + (lane >> 2);
        const float s0 = (m == 0 || m == 64) ? sc * 0.5f : sc;
        __half* base = (m < 64) ? (g_P + (((size_t)(j * 64 + m)) << 11))
                                : (g_Q + (((size_t)(j * 64 + (m - 64))) << 11));
#pragma unroll
        for (int f = 0; f < 8; f++) {
            const int col = d0 + wx * 64 + f * 8 + (lane & 3) * 2;
            *(uint32_t*)(base + col) = pack2h(acc[t16][f][0] * s0, acc[t16][f][1] * s0);
            *(uint32_t*)(base + (8 << 11) + col) = pack2h(acc[t16][f][2] * sc, acc[t16][f][3] * sc);
        }
    }
}

// ---------------- K2: norms (+ final delta, + zero vr/vi) --------------------
__global__ __launch_bounds__(256)
void norms2_kernel() {
    __shared__ float sh[8];
    const int ik = blockIdx.x;
    const int t = threadIdx.x;
    const int i = ik >> 6, k = ik & 63;

    if (ik < 8) g_vr[ik * 256 + t] = 0.0f;
    else if (ik < 16) g_vi[(ik - 8) * 256 + t] = 0.0f;

    const uint4* p = (const uint4*)(g_P + (((size_t)(i * 64 + k)) << 11));
    const uint4* q = (const uint4*)(g_Q + (((size_t)((i + 1) * 64 + k)) << 11));
    const bool last = (i == NCHUNK - 1);
    const uint4* pp = (const uint4*)(g_P + (((size_t)(30 * 64 + k)) << 11));
    const uint4* qp = (const uint4*)(g_Q + (((size_t)(31 * 64 + k)) << 11));

    // one uint4 = 8 halves per thread covers the whole 2048-row
    uint4 pv = p[t], qv = q[t];
    float s = 0.0f, dl = 0.0f;
    float cbuf[8];
    {
        const uint32_t* pw = (const uint32_t*)&pv;
        const uint32_t* qw = (const uint32_t*)&qv;
#pragma unroll
        for (int w2 = 0; w2 < 4; w2++) {
            float2 a = h2f(pw[w2]), b = h2f(qw[w2]);
            float cx = a.x + b.x, cy = a.y + b.y;
            cbuf[2 * w2] = cx; cbuf[2 * w2 + 1] = cy;
            s += cx * cx + cy * cy;
        }
    }
    if (last) {
        uint4 pv2 = pp[t], qv2 = qp[t];
        const uint32_t* pw = (const uint32_t*)&pv2;
        const uint32_t* qw = (const uint32_t*)&qv2;
#pragma unroll
        for (int w2 = 0; w2 < 4; w2++) {
            float2 a = h2f(pw[w2]), b = h2f(qw[w2]);
            float ex = cbuf[2 * w2] - a.x - b.x;
            float ey = cbuf[2 * w2 + 1] - a.y - b.y;
            dl += ex * ex + ey * ey;
        }
    }
    const int lane = t & 31, w = t >> 5;
#pragma unroll
    for (int o = 16; o > 0; o >>= 1) s += __shfl_down_sync(0xffffffffu, s, o);
    if (lane == 0) sh[w] = s;
    __syncthreads();
    if (t == 0) {
        float tot = 0.0f;
#pragma unroll
        for (int jj = 0; jj < 8; jj++) tot += sh[jj];
        g_norms[ik] = fmaxf(sqrtf(tot), 1e-12f);
    }
    if (last) {
        __syncthreads();
#pragma unroll
        for (int o = 16; o > 0; o >>= 1) dl += __shfl_down_sync(0xffffffffu, dl, o);
        if (lane == 0) sh[w] = dl;
        __syncthreads();
        if (t == 0) {
            float tot = 0.0f;
#pragma unroll
            for (int jj = 0; jj < 8; jj++) tot += sh[jj];
            g_delta[k] = sqrtf(tot);
        }
    }
}

// ---------------- K3: fused T-EMA + bind, k-split x4 -------------------------
__global__ __launch_bounds__(256)
void tbind_kernel(const float* __restrict__ rr, const float* __restrict__ ri) {
    const int i = blockIdx.x;
    const int d = (blockIdx.y << 8) + threadIdx.x;
    const int k0 = blockIdx.z << 4;
    __shared__ float winv[16];
    if (threadIdx.x < 16) {
        float w = 0.1f;
        for (int jj = i; jj < NCHUNK - 1; jj++) w *= 0.9f;
        winv[threadIdx.x] = w / g_norms[(i << 6) + k0 + threadIdx.x];
    }
    __syncthreads();
    float vr = 0.0f, vi = 0.0f;
#pragma unroll
    for (int kk = 0; kk < 16; kk++) {
        const int k = k0 + kk;
        const float c = __half2float(g_P[(((size_t)((i << 6) | k)) << 11) + d]) +
                        __half2float(g_Q[(((size_t)(((i + 1) << 6) | k)) << 11) + d]);
        const float wv = winv[kk] * c;
        vr = fmaf(wv, rr[((size_t)k << 11) + d], vr);
        vi = fmaf(wv, ri[((size_t)k << 11) + d], vi);
    }
    atomicAdd(&g_vr[d], vr);
    atomicAdd(&g_vi[d], vi);
}

// ---------------- K4a: scalars (cnorms EMA + parallel top-8) -----------------
__global__ void scalars_kernel(const float* __restrict__ wb, float* __restrict__ out) {
    __shared__ float sDelta[64], sCn[64];
    const int t = threadIdx.x;  // 64 threads
    float c = 0.0f;
#pragma unroll
    for (int i = 0; i < NCHUNK; i++) c = 0.9f * c + 0.1f * g_norms[(i << 6) + t];
    sCn[t] = c;
    const float dv = g_delta[t];
    sDelta[t] = dv;
    out[D_MODEL + t] = dv;
    __syncthreads();
    if (t < 32) {
        for (int jj = 0; jj < NRET; jj++) {
            float v0 = sDelta[t], v1 = sDelta[t + 32];
            int bi = (v1 > v0) ? (t + 32) : t;
            float bv = fmaxf(v0, v1);
#pragma unroll
            for (int o = 16; o > 0; o >>= 1) {
                float ov = __shfl_down_sync(0xffffffffu, bv, o);
                int oi = __shfl_down_sync(0xffffffffu, bi, o);
                if (ov > bv) { bv = ov; bi = oi; }
            }
            bi = __shfl_sync(0xffffffffu, bi, 0);
            if (t == 0) {
                g_top[jj] = bi;
                g_cw[jj] = log1pf(expf(wb[bi])) * fmaxf(sCn[bi], 1e-12f);
                sDelta[bi] = -3.4e38f;
            }
            __syncwarp();
        }
    }
}

// ---------------- K4b: ctx + vr/vi outputs -----------------------------------
__global__ __launch_bounds__(128)
void ctx_kernel(const float* __restrict__ rr, const float* __restrict__ ri,
                float* __restrict__ out) {
    const int d = (blockIdx.x << 7) + threadIdx.x;
    const float vr = g_vr[d], vi = g_vi[d];
    float c = 0.0f;
#pragma unroll
    for (int jj = 0; jj < NRET; jj++) {
        const int tp = g_top[jj];
        c = fmaf(g_cw[jj], fmaf(vr, rr[((size_t)tp << 11) + d], vi * ri[((size_t)tp << 11) + d]), c);
    }
    g_ctx[d] = c;
    out[D_MODEL + KBANDS + d] = vr;
    out[2 * D_MODEL + KBANDS + d] = vi;
}

// ---------------- K5: output projection --------------------------------------
__global__ __launch_bounds__(128)
void proj_kernel(const float* __restrict__ wp, const float* __restrict__ gate,
                 float* __restrict__ out) {
    __shared__ float sh[4];
    const int row = blockIdx.x;
    const int t = threadIdx.x;
    const float4* w = (const float4*)(wp + ((size_t)row << 11));
    const float4* cx = (const float4*)g_ctx;
    float s = 0.0f;
#pragma unroll
    for (int it = 0; it < 4; it++) {
        float4 a = w[t + 128 * it], b = cx[t + 128 * it];
        s += a.x * b.x + a.y * b.y + a.z * b.z + a.w * b.w;
    }
#pragma unroll
    for (int o = 16; o > 0; o >>= 1) s += __shfl_down_sync(0xffffffffu, s, o);
    if ((t & 31) == 0) sh[t >> 5] = s;
    __syncthreads();
    if (t == 0) {
        const float tot = sh[0] + sh[1] + sh[2] + sh[3];
        out[row] = tot * (1.0f / (1.0f + expf(-gate[0])));
    }
}

// ---------------- launch ------------------------------------------------------
extern "C" void kernel_launch(void* const* d_in, const int* in_sizes, int n_in,
                              void* d_out, int out_size) {
    const float* scan  = (const float*)d_in[0];
    const float* buf   = (const float*)d_in[1];
    const float* rr    = (const float*)d_in[2];
    const float* ri    = (const float*)d_in[3];
    const float* wb    = (const float*)d_in[4];
    const float* wp    = (const float*)d_in[5];
    const float* gate  = (const float*)d_in[6];
    const float* cheby = (const float*)d_in[7];
    float* out = (float*)d_out;

    static cudaStream_t s_side = nullptr;
    static cudaEvent_t ev_fork = nullptr, ev_join = nullptr;
    static bool init_done = false;
    if (!init_done) {
        cudaStreamCreateWithFlags(&s_side, cudaStreamNonBlocking);
        cudaEventCreateWithFlags(&ev_fork, cudaEventDisableTiming);
        cudaEventCreateWithFlags(&ev_join, cudaEventDisableTiming);
        init_done = true;
    }

    pq_mma<<<dim3(16, NDATA), 256>>>(scan, buf, cheby);
    norms2_kernel<<<NCHUNK * KBANDS, 256>>>();

    cudaEventRecord(ev_fork, 0);
    cudaStreamWaitEvent(s_side, ev_fork, 0);
    scalars_kernel<<<1, 64, 0, s_side>>>(wb, out);
    tbind_kernel<<<dim3(NCHUNK, 8, 4), 256>>>(rr, ri);
    cudaEventRecord(ev_join, s_side);
    cudaStreamWaitEvent(0, ev_join, 0);

    ctx_kernel<<<16, 128>>>(rr, ri, out);
    proj_kernel<<<D_MODEL, 128>>>(wp, gate, out);
}